// round 12
// baseline (speedup 1.0000x reference)
#include <cuda_runtime.h>
#include <cuda_bf16.h>
#include <cstdint>

// Problem constants
#define BB 4
#define TT 4096
#define DD 2048
#define D4 512            // DD/4 float4 lanes
#define CT 64             // output rows per block
#define NPH 32            // phases of 2 rows
#define EPS 1e-5f

#define ROWB   8192       // bytes per row in smem (512 * 16)
#define ISTG   16384      // input stage: 2 rows
#define OBOFF  (3 * ISTG)             // 49152: 2 output buffers
#define OBUFB  16384
#define PARTOFF (OBOFF + 2 * OBUFB)   // 81920: partials (2x32 phase + 48 preamble)
#define SMEMSZ  (PARTOFF + 512)       // 82432

__device__ __forceinline__ float fast_sigmoid(float v) {
    float t;
    asm("tanh.approx.f32 %0, %1;" : "=f"(t) : "f"(v * 0.5f));
    return fmaf(t, 0.5f, 0.5f);
}

__device__ __forceinline__ float warp_sum(float v) {
    #pragma unroll
    for (int o = 16; o; o >>= 1) v += __shfl_xor_sync(0xffffffffu, v, o);
    return v;
}

__device__ __forceinline__ float sq4(float4 a) {
    return a.x * a.x + a.y * a.y + a.z * a.z + a.w * a.w;
}

// ---- input: distributed LDGSTS ring (proven in R8/R11) ----
__device__ __forceinline__ void cpa16(unsigned int saddr, const float4* g) {
    asm volatile("cp.async.cg.shared.global [%0], [%1], 16;" :: "r"(saddr), "l"(g) : "memory");
}
__device__ __forceinline__ void cpa_commit() {
    asm volatile("cp.async.commit_group;" ::: "memory");
}
__device__ __forceinline__ void cpa_wait2() {
    asm volatile("cp.async.wait_group 2;" ::: "memory");
}

// ---- output: elected bulk DMA store (separate bulk-group FIFO) ----
__device__ __forceinline__ void bulk_s2g(void* gdst, unsigned int ssrc, unsigned int bytes) {
    asm volatile("cp.async.bulk.global.shared::cta.bulk_group [%0], [%1], %2;"
                 :: "l"(gdst), "r"(ssrc), "r"(bytes) : "memory");
}
__device__ __forceinline__ void bulk_commit() {
    asm volatile("cp.async.bulk.commit_group;" ::: "memory");
}
__device__ __forceinline__ void bulk_wait_read1() {
    asm volatile("cp.async.bulk.wait_group.read 1;" ::: "memory");
}
__device__ __forceinline__ void bulk_wait_all() {
    asm volatile("cp.async.bulk.wait_group 0;" ::: "memory");
}
__device__ __forceinline__ void fence_async() {
    asm volatile("fence.proxy.async.shared::cta;" ::: "memory");
}

// conv + SiLU one row; result STS'd into the staged output buffer
#define ROW_BODY_STS(XV, R, OBP)                                                \
    {                                                                           \
        float4 y3 = make_float4(XV.x * R, XV.y * R, XV.z * R, XV.w * R);        \
        float4 o;                                                               \
        o.x = w0.x * y0.x + w0.y * y1.x + w0.z * y2.x + w0.w * y3.x;            \
        o.y = w1.x * y0.y + w1.y * y1.y + w1.z * y2.y + w1.w * y3.y;            \
        o.z = w2.x * y0.z + w2.y * y1.z + w2.z * y2.z + w2.w * y3.z;            \
        o.w = w3.x * y0.w + w3.y * y1.w + w3.z * y2.w + w3.w * y3.w;            \
        o.x *= fast_sigmoid(o.x); o.y *= fast_sigmoid(o.y);                     \
        o.z *= fast_sigmoid(o.z); o.w *= fast_sigmoid(o.w);                     \
        (OBP)[tid] = o;                                                         \
        y0 = y1; y1 = y2; y2 = y3;                                              \
    }

__global__ __launch_bounds__(512, 2)
void fused_rms_dwconv_silu(const float* __restrict__ x,
                           const float* __restrict__ nw,
                           const float* __restrict__ cw,
                           float* __restrict__ out) {
    extern __shared__ unsigned char dynsmem[];
    float* part = (float*)(dynsmem + PARTOFF);   // [0..64): phase (2x32), [64..112): preamble
    const unsigned int sbase = (unsigned int)__cvta_generic_to_shared(dynsmem);

    const int tid  = threadIdx.x;          // one float4 column of D
    const int lane = tid & 31;
    const int wrp  = tid >> 5;             // 0..15
    const int b    = blockIdx.y;
    const int t0   = blockIdx.x * CT;
    const int d    = tid * 4;

    // Conv taps with norm_weight folded in.
    float4 w0 = *(const float4*)(cw + (size_t)(d + 0) * 4);
    float4 w1 = *(const float4*)(cw + (size_t)(d + 1) * 4);
    float4 w2 = *(const float4*)(cw + (size_t)(d + 2) * 4);
    float4 w3 = *(const float4*)(cw + (size_t)(d + 3) * 4);
    const float n0 = nw[d], n1 = nw[d + 1], n2 = nw[d + 2], n3 = nw[d + 3];
    w0.x *= n0; w0.y *= n0; w0.z *= n0; w0.w *= n0;
    w1.x *= n1; w1.y *= n1; w1.z *= n1; w1.w *= n1;
    w2.x *= n2; w2.y *= n2; w2.z *= n2; w2.w *= n2;
    w3.x *= n3; w3.y *= n3; w3.z *= n3; w3.w *= n3;

    const float4* xp = (const float4*)x + (size_t)b * TT * D4 + tid;
    float*        og = out + ((size_t)b * TT + t0) * DD;    // block's output base
    const float4  Z  = make_float4(0.f, 0.f, 0.f, 0.f);

    // ---- prolog: fill stage 0 (rows 0-1) and stage 1 (rows 2-3) ----
    {
        unsigned int dst0 = sbase + 0 * ISTG + tid * 16;
        const float4* s0 = xp + (size_t)(t0 + 0) * D4;
        cpa16(dst0 + 0 * ROWB, s0 + 0 * D4);
        cpa16(dst0 + 1 * ROWB, s0 + 1 * D4);
        cpa_commit();
        unsigned int dst1 = sbase + 1 * ISTG + tid * 16;
        const float4* s1 = xp + (size_t)(t0 + 2) * D4;
        cpa16(dst1 + 0 * ROWB, s1 + 0 * D4);
        cpa16(dst1 + 1 * ROWB, s1 + 1 * D4);
        cpa_commit();
    }

    // ---- halo rows t0-3..t0-1 (plain LDG, overlaps with cp.async) ----
    float4 h0 = Z, h1 = Z, h2 = Z;
    if (blockIdx.x > 0) {
        h0 = __ldg(xp + (size_t)(t0 - 3) * D4);
        h1 = __ldg(xp + (size_t)(t0 - 2) * D4);
        h2 = __ldg(xp + (size_t)(t0 - 1) * D4);
    }
    {
        float s0 = warp_sum(sq4(h0));
        float s1 = warp_sum(sq4(h1));
        float s2 = warp_sum(sq4(h2));
        if (lane == 0) {                 // preamble partials at part+64
            part[64 + 0 * 16 + wrp] = s0;
            part[64 + 1 * 16 + wrp] = s1;
            part[64 + 2 * 16 + wrp] = s2;
        }
    }
    __syncthreads();
    float4 y0, y1, y2;
    {
        float vlo = part[64 + lane];                           // rows h0,h1
        float vhi = (lane < 16) ? part[64 + lane + 32] : 0.f;  // row h2
        #pragma unroll
        for (int o = 8; o; o >>= 1) {
            vlo += __shfl_xor_sync(0xffffffffu, vlo, o);
            vhi += __shfl_xor_sync(0xffffffffu, vhi, o);
        }
        float rlo = rsqrtf(vlo * (1.0f / (float)DD) + EPS);
        float rhi = rsqrtf(vhi * (1.0f / (float)DD) + EPS);
        float rh0 = __shfl_sync(0xffffffffu, rlo, 0);
        float rh1 = __shfl_sync(0xffffffffu, rlo, 16);
        float rh2 = __shfl_sync(0xffffffffu, rhi, 0);
        y0 = make_float4(h0.x * rh0, h0.y * rh0, h0.z * rh0, h0.w * rh0);
        y1 = make_float4(h1.x * rh1, h1.y * rh1, h1.z * rh1, h1.w * rh1);
        y2 = make_float4(h2.x * rh2, h2.y * rh2, h2.z * rh2, h2.w * rh2);
    }

    // ---- main loop: 32 phases x 2 rows; LDGSTS in-ring (distance 2),
    //      staged STS output + elected bulk DMA store per phase ----
    #pragma unroll 1
    for (int p = 0; p < NPH; p++) {
        const int tb2 = p * 2;          // row offset within block chunk

        // 1. input prefetch for phase p+2 into stage (p+2)%3
        if (p + 2 < NPH) {
            unsigned int dst = sbase + ((p + 2) % 3) * ISTG + tid * 16;
            const float4* src = xp + (size_t)(t0 + (p + 2) * 2) * D4;
            cpa16(dst + 0 * ROWB, src + 0 * D4);
            cpa16(dst + 1 * ROWB, src + 1 * D4);
        }
        cpa_commit();   // empty group when guarded out keeps FIFO aligned
        cpa_wait2();    // drain the group holding THIS phase's rows

        // 2. read own column, warp partials -> buffer p&1
        const float4* buf = (const float4*)(dynsmem + (p % 3) * ISTG);
        float4 xv0 = buf[0 * D4 + tid];
        float4 xv1 = buf[1 * D4 + tid];
        float s0 = warp_sum(sq4(xv0));
        float s1 = warp_sum(sq4(xv1));
        float* pb = part + ((p & 1) << 5);
        if (lane == 0) {
            pb[wrp]      = s0;
            pb[16 + wrp] = s1;
        }

        // 3. elected: ensure bulk store p-2 finished READING outbuf[p&1]
        if (tid == 0) bulk_wait_read1();
        __syncthreads();   // bar1: partials visible + outbuf reuse published

        // 4. every warp finishes both rinvs (lanes 0-15: row0, 16-31: row1)
        float v = pb[lane];
        v += __shfl_xor_sync(0xffffffffu, v, 8);
        v += __shfl_xor_sync(0xffffffffu, v, 4);
        v += __shfl_xor_sync(0xffffffffu, v, 2);
        v += __shfl_xor_sync(0xffffffffu, v, 1);
        float rv = rsqrtf(v * (1.0f / (float)DD) + EPS);
        float r0 = __shfl_sync(0xffffffffu, rv, 0);
        float r1 = __shfl_sync(0xffffffffu, rv, 16);

        // 5. conv + SiLU, staged to smem via STS.128 (off the STG path)
        float4* ob = (float4*)(dynsmem + OBOFF + (p & 1) * OBUFB);
        ROW_BODY_STS(xv0, r0, ob);
        ROW_BODY_STS(xv1, r1, ob + D4);
        __syncthreads();   // bar2: all STS done

        // 6. elected DMA store of the 16KB output chunk
        if (tid == 0) {
            fence_async();
            bulk_s2g(og + (size_t)tb2 * DD, sbase + OBOFF + (p & 1) * OBUFB, OBUFB);
            bulk_commit();
        }
    }

    if (tid == 0) bulk_wait_all();   // drain pending stores before exit
}

extern "C" void kernel_launch(void* const* d_in, const int* in_sizes, int n_in,
                              void* d_out, int out_size) {
    const float* x  = (const float*)d_in[0];   // [B, T, D] fp32
    const float* nw = (const float*)d_in[1];   // [D] fp32
    const float* cw = (const float*)d_in[2];   // [D, 1, K=4] fp32
    float* out = (float*)d_out;                // [B, T, D] fp32

    cudaFuncSetAttribute(fused_rms_dwconv_silu,
                         cudaFuncAttributeMaxDynamicSharedMemorySize, SMEMSZ);

    dim3 grid(TT / CT, BB);
    fused_rms_dwconv_silu<<<grid, 512, SMEMSZ>>>(x, nw, cw, out);
}

// round 14
// speedup vs baseline: 1.5006x; 1.5006x over previous
#include <cuda_runtime.h>
#include <cuda_bf16.h>
#include <cstdint>

// Problem constants
#define BB 4
#define TT 4096
#define DD 2048
#define D4 512            // DD/4 float4 lanes
#define CT 32             // output rows per block (was 64): grid 512 keeps all
                          // 296 co-resident block slots fed (~+14% concurrency)
#define NPH 8             // phases of 4 rows
#define EPS 1e-5f

#define ROWB   8192       // bytes per row in smem (512 * 16)
#define STAGEB 32768      // 4 rows per stage
#define NSTAGE 3
#define PARTOFF (NSTAGE * STAGEB)       // 98304: 2 x 64 float partials
#define SMEMSZ  (PARTOFF + 512)

__device__ __forceinline__ float fast_sigmoid(float v) {
    float t;
    asm("tanh.approx.f32 %0, %1;" : "=f"(t) : "f"(v * 0.5f));
    return fmaf(t, 0.5f, 0.5f);
}

__device__ __forceinline__ float warp_sum(float v) {
    #pragma unroll
    for (int o = 16; o; o >>= 1) v += __shfl_xor_sync(0xffffffffu, v, o);
    return v;
}

__device__ __forceinline__ float sq4(float4 a) {
    return a.x * a.x + a.y * a.y + a.z * a.z + a.w * a.w;
}

__device__ __forceinline__ void cpa16(unsigned int saddr, const float4* g) {
    asm volatile("cp.async.cg.shared.global [%0], [%1], 16;" :: "r"(saddr), "l"(g) : "memory");
}
__device__ __forceinline__ void cpa_commit() {
    asm volatile("cp.async.commit_group;" ::: "memory");
}
__device__ __forceinline__ void cpa_wait2() {
    asm volatile("cp.async.wait_group 2;" ::: "memory");
}

#define ROW_BODY(XV, R, TOFF)                                                   \
    {                                                                           \
        float4 y3 = make_float4(XV.x * R, XV.y * R, XV.z * R, XV.w * R);        \
        float4 o;                                                               \
        o.x = w0.x * y0.x + w0.y * y1.x + w0.z * y2.x + w0.w * y3.x;            \
        o.y = w1.x * y0.y + w1.y * y1.y + w1.z * y2.y + w1.w * y3.y;            \
        o.z = w2.x * y0.z + w2.y * y1.z + w2.z * y2.z + w2.w * y3.z;            \
        o.w = w3.x * y0.w + w3.y * y1.w + w3.z * y2.w + w3.w * y3.w;            \
        o.x *= fast_sigmoid(o.x); o.y *= fast_sigmoid(o.y);                     \
        o.z *= fast_sigmoid(o.z); o.w *= fast_sigmoid(o.w);                     \
        __stcs(op + (size_t)(TOFF) * D4, o);                                    \
        y0 = y1; y1 = y2; y2 = y3;                                              \
    }

__global__ __launch_bounds__(512, 2)
void fused_rms_dwconv_silu(const float* __restrict__ x,
                           const float* __restrict__ nw,
                           const float* __restrict__ cw,
                           float* __restrict__ out) {
    extern __shared__ unsigned char dynsmem[];
    float* part = (float*)(dynsmem + PARTOFF);   // 2 x 64 floats (double-buffered)
    const unsigned int sbase = (unsigned int)__cvta_generic_to_shared(dynsmem);

    const int tid  = threadIdx.x;          // one float4 column of D
    const int lane = tid & 31;
    const int wrp  = tid >> 5;             // 0..15
    const int b    = blockIdx.y;
    const int t0   = blockIdx.x * CT;
    const int d    = tid * 4;

    // Conv taps with norm_weight folded in.
    float4 w0 = *(const float4*)(cw + (size_t)(d + 0) * 4);
    float4 w1 = *(const float4*)(cw + (size_t)(d + 1) * 4);
    float4 w2 = *(const float4*)(cw + (size_t)(d + 2) * 4);
    float4 w3 = *(const float4*)(cw + (size_t)(d + 3) * 4);
    const float n0 = nw[d], n1 = nw[d + 1], n2 = nw[d + 2], n3 = nw[d + 3];
    w0.x *= n0; w0.y *= n0; w0.z *= n0; w0.w *= n0;
    w1.x *= n1; w1.y *= n1; w1.z *= n1; w1.w *= n1;
    w2.x *= n2; w2.y *= n2; w2.z *= n2; w2.w *= n2;
    w3.x *= n3; w3.y *= n3; w3.z *= n3; w3.w *= n3;

    const float4* xp = (const float4*)x + (size_t)b * TT * D4 + tid;
    float4*       op = (float4*)out     + (size_t)b * TT * D4 + tid;
    const float4  Z  = make_float4(0.f, 0.f, 0.f, 0.f);

    // ---- prolog: kick G(-2) (phase 0 -> stage 0) and G(-1) (phase 1 -> stage 1)
    {
        unsigned int dst0 = sbase + 0 * STAGEB + tid * 16;
        const float4* s0 = xp + (size_t)(t0 + 0) * D4;
        cpa16(dst0 + 0 * ROWB, s0 + 0 * D4);
        cpa16(dst0 + 1 * ROWB, s0 + 1 * D4);
        cpa16(dst0 + 2 * ROWB, s0 + 2 * D4);
        cpa16(dst0 + 3 * ROWB, s0 + 3 * D4);
        cpa_commit();
        unsigned int dst1 = sbase + 1 * STAGEB + tid * 16;
        const float4* s1 = xp + (size_t)(t0 + 4) * D4;
        cpa16(dst1 + 0 * ROWB, s1 + 0 * D4);
        cpa16(dst1 + 1 * ROWB, s1 + 1 * D4);
        cpa16(dst1 + 2 * ROWB, s1 + 2 * D4);
        cpa16(dst1 + 3 * ROWB, s1 + 3 * D4);
        cpa_commit();
    }

    // ---- halo rows t0-3..t0-1 (plain LDG, overlaps with cp.async) ----
    float4 h0 = Z, h1 = Z, h2 = Z;
    if (blockIdx.x > 0) {
        h0 = __ldg(xp + (size_t)(t0 - 3) * D4);
        h1 = __ldg(xp + (size_t)(t0 - 2) * D4);
        h2 = __ldg(xp + (size_t)(t0 - 1) * D4);
    }
    {
        // halo partials in buffer 1 (phase 0 uses buffer 0)
        float s0 = warp_sum(sq4(h0));
        float s1 = warp_sum(sq4(h1));
        float s2 = warp_sum(sq4(h2));
        if (lane == 0) {
            part[64 + 0 * 16 + wrp] = s0;
            part[64 + 1 * 16 + wrp] = s1;
            part[64 + 2 * 16 + wrp] = s2;
        }
    }
    __syncthreads();
    float4 y0, y1, y2;
    {
        float vlo = part[64 + lane];                           // rows h0,h1
        float vhi = (lane < 16) ? part[64 + lane + 32] : 0.f;  // row h2
        #pragma unroll
        for (int o = 8; o; o >>= 1) {
            vlo += __shfl_xor_sync(0xffffffffu, vlo, o);
            vhi += __shfl_xor_sync(0xffffffffu, vhi, o);
        }
        float rlo = rsqrtf(vlo * (1.0f / (float)DD) + EPS);
        float rhi = rsqrtf(vhi * (1.0f / (float)DD) + EPS);
        float rh0 = __shfl_sync(0xffffffffu, rlo, 0);
        float rh1 = __shfl_sync(0xffffffffu, rlo, 16);
        float rh2 = __shfl_sync(0xffffffffu, rhi, 0);
        y0 = make_float4(h0.x * rh0, h0.y * rh0, h0.z * rh0, h0.w * rh0);
        y1 = make_float4(h1.x * rh1, h1.y * rh1, h1.z * rh1, h1.w * rh1);
        y2 = make_float4(h2.x * rh2, h2.y * rh2, h2.z * rh2, h2.w * rh2);
    }

    // ---- main loop: 8 phases x 4 rows, 3-stage LDGSTS ring, distance-2
    //      prefetch, ONE block barrier per phase ----
    #pragma unroll 1
    for (int p = 0; p < NPH; p++) {
        const int tb = t0 + p * 4;

        // 1. prefetch phase p+2 into stage (p+2)%3 == (p-1)%3. Only this
        //    thread read that stage (its own bytes), at phase p-1 — program
        //    order makes the overwrite safe.
        if (p + 2 < NPH) {
            unsigned int dst = sbase + ((p + 2) % 3) * STAGEB + tid * 16;
            const float4* src = xp + (size_t)(t0 + (p + 2) * 4) * D4;
            cpa16(dst + 0 * ROWB, src + 0 * D4);
            cpa16(dst + 1 * ROWB, src + 1 * D4);
            cpa16(dst + 2 * ROWB, src + 2 * D4);
            cpa16(dst + 3 * ROWB, src + 3 * D4);
        }
        cpa_commit();   // empty group when guarded out keeps FIFO aligned

        // 2. three groups pending -> wait_group 2 drains the group holding
        //    THIS phase's data (full 2-phase lead preserved).
        cpa_wait2();

        // 3. read own column of the 4 rows, warp partials -> buffer p&1
        const float4* buf = (const float4*)(dynsmem + (p % 3) * STAGEB);
        float4 xv0 = buf[0 * D4 + tid];
        float4 xv1 = buf[1 * D4 + tid];
        float4 xv2 = buf[2 * D4 + tid];
        float4 xv3 = buf[3 * D4 + tid];
        float s0 = warp_sum(sq4(xv0));
        float s1 = warp_sum(sq4(xv1));
        float s2 = warp_sum(sq4(xv2));
        float s3 = warp_sum(sq4(xv3));
        float* pb = part + ((p & 1) << 6);
        if (lane == 0) {
            pb[0 * 16 + wrp] = s0;
            pb[1 * 16 + wrp] = s1;
            pb[2 * 16 + wrp] = s2;
            pb[3 * 16 + wrp] = s3;
        }
        __syncthreads();   // the ONLY barrier: publishes partials

        // 4. redundant finish: every warp computes all 4 rinvs
        float vlo = pb[lane];          // rows 0 (lanes 0-15), 1 (16-31)
        float vhi = pb[lane + 32];     // rows 2, 3
        #pragma unroll
        for (int o = 8; o; o >>= 1) {
            vlo += __shfl_xor_sync(0xffffffffu, vlo, o);
            vhi += __shfl_xor_sync(0xffffffffu, vhi, o);
        }
        float rlo = rsqrtf(vlo * (1.0f / (float)DD) + EPS);
        float rhi = rsqrtf(vhi * (1.0f / (float)DD) + EPS);
        float r0 = __shfl_sync(0xffffffffu, rlo, 0);
        float r1 = __shfl_sync(0xffffffffu, rlo, 16);
        float r2 = __shfl_sync(0xffffffffu, rhi, 0);
        float r3 = __shfl_sync(0xffffffffu, rhi, 16);

        // 5. conv + SiLU + streaming stores
        ROW_BODY(xv0, r0, tb + 0);
        ROW_BODY(xv1, r1, tb + 1);
        ROW_BODY(xv2, r2, tb + 2);
        ROW_BODY(xv3, r3, tb + 3);
    }
}

extern "C" void kernel_launch(void* const* d_in, const int* in_sizes, int n_in,
                              void* d_out, int out_size) {
    const float* x  = (const float*)d_in[0];   // [B, T, D] fp32
    const float* nw = (const float*)d_in[1];   // [D] fp32
    const float* cw = (const float*)d_in[2];   // [D, 1, K=4] fp32
    float* out = (float*)d_out;                // [B, T, D] fp32

    cudaFuncSetAttribute(fused_rms_dwconv_silu,
                         cudaFuncAttributeMaxDynamicSharedMemorySize, SMEMSZ);

    dim3 grid(TT / CT, BB);   // 128 x 4 = 512 blocks
    fused_rms_dwconv_silu<<<grid, 512, SMEMSZ>>>(x, nw, cw, out);
}

// round 16
// speedup vs baseline: 1.5535x; 1.0353x over previous
#include <cuda_runtime.h>
#include <cuda_bf16.h>
#include <cstdint>

// Problem constants
#define BB 4
#define TT 4096
#define DD 2048
#define D4 512            // DD/4 float4 lanes
#define CT 64             // output rows per block
#define NPH 16            // phases of 4 rows
#define EPS 1e-5f

#define ROWB   8192       // bytes per row in smem (512 * 16)
#define STAGEB 32768      // 4 rows per stage
#define NSTAGE 3
#define PARTOFF (NSTAGE * STAGEB)       // 98304
#define SMEMSZ  (PARTOFF + 512)

__device__ __forceinline__ float fast_sigmoid(float v) {
    float t;
    asm("tanh.approx.f32 %0, %1;" : "=f"(t) : "f"(v * 0.5f));
    return fmaf(t, 0.5f, 0.5f);
}

__device__ __forceinline__ float warp_sum(float v) {
    #pragma unroll
    for (int o = 16; o; o >>= 1) v += __shfl_xor_sync(0xffffffffu, v, o);
    return v;
}

__device__ __forceinline__ float sq4(float4 a) {
    return a.x * a.x + a.y * a.y + a.z * a.z + a.w * a.w;
}

__device__ __forceinline__ void cpa16(unsigned int saddr, const float4* g) {
    asm volatile("cp.async.cg.shared.global [%0], [%1], 16;" :: "r"(saddr), "l"(g) : "memory");
}
__device__ __forceinline__ void cpa_commit() {
    asm volatile("cp.async.commit_group;" ::: "memory");
}
__device__ __forceinline__ void cpa_wait1() {
    asm volatile("cp.async.wait_group 1;" ::: "memory");
}

#define ROW_BODY(XV, R, TOFF)                                                   \
    {                                                                           \
        float4 y3 = make_float4(XV.x * R, XV.y * R, XV.z * R, XV.w * R);        \
        float4 o;                                                               \
        o.x = w0.x * y0.x + w0.y * y1.x + w0.z * y2.x + w0.w * y3.x;            \
        o.y = w1.x * y0.y + w1.y * y1.y + w1.z * y2.y + w1.w * y3.y;            \
        o.z = w2.x * y0.z + w2.y * y1.z + w2.z * y2.z + w2.w * y3.z;            \
        o.w = w3.x * y0.w + w3.y * y1.w + w3.z * y2.w + w3.w * y3.w;            \
        o.x *= fast_sigmoid(o.x); o.y *= fast_sigmoid(o.y);                     \
        o.z *= fast_sigmoid(o.z); o.w *= fast_sigmoid(o.w);                     \
        __stcs(op + (size_t)(TOFF) * D4, o);                                    \
        y0 = y1; y1 = y2; y2 = y3;                                              \
    }

__global__ __launch_bounds__(512, 2)
void fused_rms_dwconv_silu(const float* __restrict__ x,
                           const float* __restrict__ nw,
                           const float* __restrict__ cw,
                           float* __restrict__ out) {
    extern __shared__ unsigned char dynsmem[];
    float* part = (float*)(dynsmem + PARTOFF);   // 2 x 64 floats (double-buffered)
    const unsigned int sbase = (unsigned int)__cvta_generic_to_shared(dynsmem);

    const int tid  = threadIdx.x;          // one float4 column of D
    const int lane = tid & 31;
    const int wrp  = tid >> 5;             // 0..15
    const int b    = blockIdx.y;
    const int t0   = blockIdx.x * CT;
    const int d    = tid * 4;
    const bool lohalf = (lane < 16);

    // Conv taps with norm_weight folded in.
    float4 w0 = *(const float4*)(cw + (size_t)(d + 0) * 4);
    float4 w1 = *(const float4*)(cw + (size_t)(d + 1) * 4);
    float4 w2 = *(const float4*)(cw + (size_t)(d + 2) * 4);
    float4 w3 = *(const float4*)(cw + (size_t)(d + 3) * 4);
    const float n0 = nw[d], n1 = nw[d + 1], n2 = nw[d + 2], n3 = nw[d + 3];
    w0.x *= n0; w0.y *= n0; w0.z *= n0; w0.w *= n0;
    w1.x *= n1; w1.y *= n1; w1.z *= n1; w1.w *= n1;
    w2.x *= n2; w2.y *= n2; w2.z *= n2; w2.w *= n2;
    w3.x *= n3; w3.y *= n3; w3.z *= n3; w3.w *= n3;

    const float4* xp = (const float4*)x + (size_t)b * TT * D4 + tid;
    float4*       op = (float4*)out     + (size_t)b * TT * D4 + tid;
    const float4  Z  = make_float4(0.f, 0.f, 0.f, 0.f);

    // ---- prolog: kick G0 (phase 0 -> stage 0) and G1 (phase 1 -> stage 1) ----
    {
        unsigned int dst0 = sbase + 0 * STAGEB + tid * 16;
        const float4* s0 = xp + (size_t)(t0 + 0) * D4;
        cpa16(dst0 + 0 * ROWB, s0 + 0 * D4);
        cpa16(dst0 + 1 * ROWB, s0 + 1 * D4);
        cpa16(dst0 + 2 * ROWB, s0 + 2 * D4);
        cpa16(dst0 + 3 * ROWB, s0 + 3 * D4);
        cpa_commit();
        unsigned int dst1 = sbase + 1 * STAGEB + tid * 16;
        const float4* s1 = xp + (size_t)(t0 + 4) * D4;
        cpa16(dst1 + 0 * ROWB, s1 + 0 * D4);
        cpa16(dst1 + 1 * ROWB, s1 + 1 * D4);
        cpa16(dst1 + 2 * ROWB, s1 + 2 * D4);
        cpa16(dst1 + 3 * ROWB, s1 + 3 * D4);
        cpa_commit();
    }

    // ---- halo rows t0-3..t0-1 (plain LDG, overlaps with cp.async) ----
    float4 h0 = Z, h1 = Z, h2 = Z;
    if (blockIdx.x > 0) {
        h0 = __ldg(xp + (size_t)(t0 - 3) * D4);
        h1 = __ldg(xp + (size_t)(t0 - 2) * D4);
        h2 = __ldg(xp + (size_t)(t0 - 1) * D4);
    }
    {
        float s0 = warp_sum(sq4(h0));
        float s1 = warp_sum(sq4(h1));
        float s2 = warp_sum(sq4(h2));
        if (lane == 0) {                // halo partials in buffer 1
            part[64 + 0 * 16 + wrp] = s0;
            part[64 + 1 * 16 + wrp] = s1;
            part[64 + 2 * 16 + wrp] = s2;
        }
    }
    __syncthreads();
    float4 y0, y1, y2;
    {
        float vlo = part[64 + lane];                       // h0 | h1 halves
        float vhi = lohalf ? part[64 + lane + 32] : 0.f;   // h2 | -
        #pragma unroll
        for (int o = 8; o; o >>= 1) {
            vlo += __shfl_xor_sync(0xffffffffu, vlo, o);
            vhi += __shfl_xor_sync(0xffffffffu, vhi, o);
        }
        float rlo = rsqrtf(vlo * (1.0f / (float)DD) + EPS);
        float rhi = rsqrtf(vhi * (1.0f / (float)DD) + EPS);
        float rh0 = __shfl_sync(0xffffffffu, rlo, 0);
        float rh1 = __shfl_sync(0xffffffffu, rlo, 16);
        float rh2 = __shfl_sync(0xffffffffu, rhi, 0);
        y0 = make_float4(h0.x * rh0, h0.y * rh0, h0.z * rh0, h0.w * rh0);
        y1 = make_float4(h1.x * rh1, h1.y * rh1, h1.z * rh1, h1.w * rh1);
        y2 = make_float4(h2.x * rh2, h2.y * rh2, h2.z * rh2, h2.w * rh2);
    }
    cpa_wait1();          // G0 complete (G1 may pend)
    __syncthreads();      // publish G0 data + protect part[]

    // ---- main loop: 16 phases x 4 rows (R8 schedule) ----
    #pragma unroll 1
    for (int p = 0; p < NPH; p++) {
        const int tb = t0 + p * 4;

        // 1. prefetch phase p+2 into stage (p+2)%3
        if (p + 2 < NPH) {
            unsigned int dst = sbase + ((p + 2) % 3) * STAGEB + tid * 16;
            const float4* src = xp + (size_t)(t0 + (p + 2) * 4) * D4;
            cpa16(dst + 0 * ROWB, src + 0 * D4);
            cpa16(dst + 1 * ROWB, src + 1 * D4);
            cpa16(dst + 2 * ROWB, src + 2 * D4);
            cpa16(dst + 3 * ROWB, src + 3 * D4);
        }
        cpa_commit();   // empty group when guarded out keeps FIFO aligned

        // 2. read 4 rows, warp partials -> buffer p&1
        const float4* buf = (const float4*)(dynsmem + (p % 3) * STAGEB);
        float4 xv0 = buf[0 * D4 + tid];
        float4 xv1 = buf[1 * D4 + tid];
        float4 xv2 = buf[2 * D4 + tid];
        float4 xv3 = buf[3 * D4 + tid];
        float s0 = warp_sum(sq4(xv0));
        float s1 = warp_sum(sq4(xv1));
        float s2 = warp_sum(sq4(xv2));
        float s3 = warp_sum(sq4(xv3));
        float* pb = part + ((p & 1) << 6);
        if (lane == 0) {
            pb[0 * 16 + wrp] = s0;
            pb[1 * 16 + wrp] = s1;
            pb[2 * 16 + wrp] = s2;
            pb[3 * 16 + wrp] = s3;
        }
        __syncthreads();   // bar A: partials visible

        // 3. stage-2 finish, broadcast-free: butterfly halves, rsqrt on the
        //    halves, ONE xor-16 swap of the rinvs, ALU selects (no bcast shfls)
        float vlo = pb[lane];          // rows 0 | 1 by half
        float vhi = pb[lane + 32];     // rows 2 | 3 by half
        #pragma unroll
        for (int o = 8; o; o >>= 1) {
            vlo += __shfl_xor_sync(0xffffffffu, vlo, o);
            vhi += __shfl_xor_sync(0xffffffffu, vhi, o);
        }
        float rmine_lo = rsqrtf(vlo * (1.0f / (float)DD) + EPS);  // row0|row1
        float rmine_hi = rsqrtf(vhi * (1.0f / (float)DD) + EPS);  // row2|row3
        float rothr_lo = __shfl_xor_sync(0xffffffffu, rmine_lo, 16);
        float rothr_hi = __shfl_xor_sync(0xffffffffu, rmine_hi, 16);
        float r0 = lohalf ? rmine_lo : rothr_lo;
        float r1 = lohalf ? rothr_lo : rmine_lo;
        float r2 = lohalf ? rmine_hi : rothr_hi;
        float r3 = lohalf ? rothr_hi : rmine_hi;

        // 4. conv + SiLU + streaming stores
        ROW_BODY(xv0, r0, tb + 0);
        ROW_BODY(xv1, r1, tb + 1);
        ROW_BODY(xv2, r2, tb + 2);
        ROW_BODY(xv3, r3, tb + 3);

        // 5. drain next phase's group, publish (R8 schedule)
        cpa_wait1();
        __syncthreads();   // bar B
    }
}

extern "C" void kernel_launch(void* const* d_in, const int* in_sizes, int n_in,
                              void* d_out, int out_size) {
    const float* x  = (const float*)d_in[0];   // [B, T, D] fp32
    const float* nw = (const float*)d_in[1];   // [D] fp32
    const float* cw = (const float*)d_in[2];   // [D, 1, K=4] fp32
    float* out = (float*)d_out;                // [B, T, D] fp32

    cudaFuncSetAttribute(fused_rms_dwconv_silu,
                         cudaFuncAttributeMaxDynamicSharedMemorySize, SMEMSZ);

    dim3 grid(TT / CT, BB);   // 64 x 4 = 256 blocks
    fused_rms_dwconv_silu<<<grid, 512, SMEMSZ>>>(x, nw, cw, out);
}